// round 1
// baseline (speedup 1.0000x reference)
#include <cuda_runtime.h>

// RandomShiftsAug: the reference's grid_sample reduces EXACTLY to an integer
// gather from the replicate-padded (pad=4) image:
//   out[n,c,i,j] = x[n,c, clamp(i+sy-4,0,H-1), clamp(j+sx-4,0,W-1)]
// because ah/aw are pixel centers of the padded image and the shift scale is
// exactly 2/H2 normalized units (= 1 pixel) per shift step.

#define N_  128
#define C_  9
#define H_  224
#define W_  224
#define PAD_ 4

__global__ __launch_bounds__(224) void random_shift_kernel(
    const float* __restrict__ x,
    const int*   __restrict__ shift,
    float*       __restrict__ out)
{
    // blockIdx.x : row tile (4 rows each), 56 tiles
    // blockIdx.y : nc = n*C_ + c, 1152 values
    const int nc = blockIdx.y;
    const int n  = nc / C_;

    const int sx = shift[2 * n + 0];   // width shift  (grid[...,0])
    const int sy = shift[2 * n + 1];   // height shift (grid[...,1])
    const int dx = sx - PAD_;          // in [-4, 4]
    const int dy = sy - PAD_;

    const int i = blockIdx.x * 4 + threadIdx.y;          // output row
    int si = i + dy;
    si = si < 0 ? 0 : (si > H_ - 1 ? H_ - 1 : si);       // replicate clamp

    const size_t img = (size_t)nc * (H_ * W_);
    const float* __restrict__ row = x + img + (size_t)si * W_;

    const int j0 = threadIdx.x * 4;                      // output col (float4)

    int ja = j0 + 0 + dx;
    int jb = j0 + 1 + dx;
    int jc = j0 + 2 + dx;
    int jd = j0 + 3 + dx;
    ja = ja < 0 ? 0 : (ja > W_ - 1 ? W_ - 1 : ja);
    jb = jb < 0 ? 0 : (jb > W_ - 1 ? W_ - 1 : jb);
    jc = jc < 0 ? 0 : (jc > W_ - 1 ? W_ - 1 : jc);
    jd = jd < 0 ? 0 : (jd > W_ - 1 ? W_ - 1 : jd);

    float4 v;
    v.x = __ldg(row + ja);
    v.y = __ldg(row + jb);
    v.z = __ldg(row + jc);
    v.w = __ldg(row + jd);

    float4* __restrict__ dst =
        (float4*)(out + img + (size_t)i * W_ + j0);
    *dst = v;
}

extern "C" void kernel_launch(void* const* d_in, const int* in_sizes, int n_in,
                              void* d_out, int out_size)
{
    const float* x     = (const float*)d_in[0];
    const int*   shift = (const int*)d_in[1];
    float*       out   = (float*)d_out;

    dim3 block(56, 4);          // 56 float4-cols x 4 rows = 224 threads
    dim3 grid(H_ / 4, N_ * C_); // (56 row-tiles, 1152 images*channels)
    random_shift_kernel<<<grid, block>>>(x, shift, out);
}

// round 2
// speedup vs baseline: 1.0585x; 1.0585x over previous
#include <cuda_runtime.h>

// RandomShiftsAug == integer gather from the replicate-padded (pad=4) image:
//   out[n,c,i,j] = x[n,c, clamp(i+sy-4,0,223), clamp(j+sx-4,0,223)]
// R2: 4 output rows per thread -> 16 independent LDGs in flight (MLP=16)
// to hide DRAM latency; j-clamp arithmetic hoisted across rows.

#define N_   128
#define C_   9
#define H_   224
#define W_   224
#define PAD_ 4

__global__ __launch_bounds__(224) void random_shift_kernel(
    const float* __restrict__ x,
    const int*   __restrict__ shift,
    float*       __restrict__ out)
{
    const int nc = blockIdx.y;           // n*C_ + c, 1152 values
    const int n  = nc / C_;

    const int dx = shift[2 * n + 0] - PAD_;   // width shift,  [-4,4]
    const int dy = shift[2 * n + 1] - PAD_;   // height shift, [-4,4]

    // column indices: same for all 4 rows this thread handles
    const int j0 = threadIdx.x * 4;
    int ja = j0 + 0 + dx;
    int jb = j0 + 1 + dx;
    int jc = j0 + 2 + dx;
    int jd = j0 + 3 + dx;
    ja = ja < 0 ? 0 : (ja > W_ - 1 ? W_ - 1 : ja);
    jb = jb < 0 ? 0 : (jb > W_ - 1 ? W_ - 1 : jb);
    jc = jc < 0 ? 0 : (jc > W_ - 1 ? W_ - 1 : jc);
    jd = jd < 0 ? 0 : (jd > W_ - 1 ? W_ - 1 : jd);

    const size_t img = (size_t)nc * (H_ * W_);
    const int i0 = blockIdx.x * 16 + threadIdx.y;   // rows i0, i0+4, i0+8, i0+12

    const float* __restrict__ src[4];
    #pragma unroll
    for (int r = 0; r < 4; r++) {
        int si = i0 + 4 * r + dy;
        si = si < 0 ? 0 : (si > H_ - 1 ? H_ - 1 : si);
        src[r] = x + img + (size_t)si * W_;
    }

    // issue all 16 loads before any store (max memory-level parallelism)
    float4 v[4];
    #pragma unroll
    for (int r = 0; r < 4; r++) {
        v[r].x = __ldg(src[r] + ja);
        v[r].y = __ldg(src[r] + jb);
        v[r].z = __ldg(src[r] + jc);
        v[r].w = __ldg(src[r] + jd);
    }

    #pragma unroll
    for (int r = 0; r < 4; r++) {
        float4* __restrict__ dst =
            (float4*)(out + img + (size_t)(i0 + 4 * r) * W_ + j0);
        *dst = v[r];
    }
}

extern "C" void kernel_launch(void* const* d_in, const int* in_sizes, int n_in,
                              void* d_out, int out_size)
{
    const float* x     = (const float*)d_in[0];
    const int*   shift = (const int*)d_in[1];
    float*       out   = (float*)d_out;

    dim3 block(56, 4);            // 56 float4-cols x 4 row-slots = 224 threads
    dim3 grid(H_ / 16, N_ * C_);  // (14 row-tiles of 16 rows, 1152 nc)
    random_shift_kernel<<<grid, block>>>(x, shift, out);
}

// round 3
// speedup vs baseline: 1.0817x; 1.0219x over previous
#include <cuda_runtime.h>

// RandomShiftsAug == integer gather from the replicate-padded (pad=4) image:
//   out[n,c,i,j] = x[n,c, clamp(i+sy-4,0,223), clamp(j+sx-4,0,223)]
// R3: 8 output rows per thread -> 32 independent LDGs in flight; streaming
// cache hints (__ldcs/__stcs) since there is zero data reuse.

#define N_   128
#define C_   9
#define H_   224
#define W_   224
#define PAD_ 4
#define ROWS_ 8

__global__ __launch_bounds__(224) void random_shift_kernel(
    const float* __restrict__ x,
    const int*   __restrict__ shift,
    float*       __restrict__ out)
{
    const int nc = blockIdx.y;           // n*C_ + c, 1152 values
    const int n  = nc / C_;

    const int dx = shift[2 * n + 0] - PAD_;   // width shift,  [-4,4]
    const int dy = shift[2 * n + 1] - PAD_;   // height shift, [-4,4]

    // column indices: shared by all ROWS_ rows this thread handles
    const int j0 = threadIdx.x * 4;
    int ja = j0 + 0 + dx;
    int jb = j0 + 1 + dx;
    int jc = j0 + 2 + dx;
    int jd = j0 + 3 + dx;
    ja = ja < 0 ? 0 : (ja > W_ - 1 ? W_ - 1 : ja);
    jb = jb < 0 ? 0 : (jb > W_ - 1 ? W_ - 1 : jb);
    jc = jc < 0 ? 0 : (jc > W_ - 1 ? W_ - 1 : jc);
    jd = jd < 0 ? 0 : (jd > W_ - 1 ? W_ - 1 : jd);

    const size_t img = (size_t)nc * (H_ * W_);
    const int i0 = blockIdx.x * (4 * ROWS_) + threadIdx.y;  // rows i0 + 4*r

    const float* __restrict__ src[ROWS_];
    #pragma unroll
    for (int r = 0; r < ROWS_; r++) {
        int si = i0 + 4 * r + dy;
        si = si < 0 ? 0 : (si > H_ - 1 ? H_ - 1 : si);
        src[r] = x + img + (size_t)si * W_;
    }

    // issue all 32 loads before any store (max memory-level parallelism)
    float4 v[ROWS_];
    #pragma unroll
    for (int r = 0; r < ROWS_; r++) {
        v[r].x = __ldcs(src[r] + ja);
        v[r].y = __ldcs(src[r] + jb);
        v[r].z = __ldcs(src[r] + jc);
        v[r].w = __ldcs(src[r] + jd);
    }

    #pragma unroll
    for (int r = 0; r < ROWS_; r++) {
        float4* dst = (float4*)(out + img + (size_t)(i0 + 4 * r) * W_ + j0);
        __stcs(dst, v[r]);
    }
}

extern "C" void kernel_launch(void* const* d_in, const int* in_sizes, int n_in,
                              void* d_out, int out_size)
{
    const float* x     = (const float*)d_in[0];
    const int*   shift = (const int*)d_in[1];
    float*       out   = (float*)d_out;

    dim3 block(56, 4);                      // 224 threads
    dim3 grid(H_ / (4 * ROWS_), N_ * C_);   // (7 row-tiles of 32 rows, 1152 nc)
    random_shift_kernel<<<grid, block>>>(x, shift, out);
}